// round 6
// baseline (speedup 1.0000x reference)
#include <cuda_runtime.h>
#include <cstdint>

// ---------------------------------------------------------------------------
// B=2, N=1024, D=1024, K=8 (circulant), H=16, dh=64
// circ_linear == dense GEMM with W[p*8+i][q*8+j] = w[p,q,(i-j) mod 8]
// ---------------------------------------------------------------------------
constexpr int DD = 1024;
constexpr int MM = 2048;

__device__ float g_We[4][DD * DD];   // expanded weights, layout B[k][n]
__device__ float g_Q[MM * DD];
__device__ float g_K[MM * DD];
__device__ float g_V[MM * DD];
__device__ float g_O[MM * DD];

__device__ __forceinline__ uint32_t f2tf32(float f) {
    uint32_t r;
    asm("cvt.rna.tf32.f32 %0, %1;" : "=r"(r) : "f"(f));
    return r;
}

#define MMA_TF32(ACC, A0, A1, A2, A3, B0, B1)                            \
    asm volatile(                                                        \
        "mma.sync.aligned.m16n8k8.row.col.f32.tf32.tf32.f32 "            \
        "{%0,%1,%2,%3}, {%4,%5,%6,%7}, {%8,%9}, {%0,%1,%2,%3};"          \
        : "+f"((ACC)[0]), "+f"((ACC)[1]), "+f"((ACC)[2]), "+f"((ACC)[3]) \
        : "r"(A0), "r"(A1), "r"(A2), "r"(A3), "r"(B0), "r"(B1))

#define MMA_TF32V(ACC, AF, BF)                                           \
    MMA_TF32(ACC, (AF)[0], (AF)[1], (AF)[2], (AF)[3], (BF)[0], (BF)[1])

// ---------------------------------------------------------------------------
// Expand circulant blocks: dst[k][n] = w[n/8][k/8][(n-k)&7]
// ---------------------------------------------------------------------------
__global__ void expand_kernel(const float* __restrict__ w0,
                              const float* __restrict__ w1,
                              const float* __restrict__ w2,
                              const float* __restrict__ w3)
{
    const float* w;
    switch (blockIdx.y) {
        case 0:  w = w0; break;
        case 1:  w = w1; break;
        case 2:  w = w2; break;
        default: w = w3; break;
    }
    float* dst = g_We[blockIdx.y];
    int idx = blockIdx.x * 256 + threadIdx.x;
    int k = idx >> 10;
    int n = idx & 1023;
    dst[idx] = w[((n >> 3) << 10) + ((k >> 3) << 3) + ((n - k) & 7)];
}

// ---------------------------------------------------------------------------
// TF32 GEMM + bias, tile 128x128, BK=16, 256 threads, 8 warps of 32x64.
// FRAGMENT-MAJOR smem: tiles stored pre-permuted into mma fragment order
// (tf32-converted at staging), so the inner loop uses only LDS.128.
//   AsF[buf][(kc*8 + m16tile)*32 + lane] : uint4 = lane's 4 A-regs
//   BsF[buf][(kc*8 + n8pair )*32 + lane] : uint4 = lane's B-regs for the
//                                          even/odd n8 tiles of the pair
// ---------------------------------------------------------------------------
__global__ __launch_bounds__(256, 2)
void gemm_tf32(const float* __restrict__ A,
               const float* __restrict__ B0, const float* __restrict__ B1,
               const float* __restrict__ B2,
               const float* __restrict__ bi0, const float* __restrict__ bi1,
               const float* __restrict__ bi2,
               float* __restrict__ C0, float* __restrict__ C1,
               float* __restrict__ C2)
{
    const float* Bm; const float* bias; float* C;
    if (blockIdx.z == 0)      { Bm = B0; bias = bi0; C = C0; }
    else if (blockIdx.z == 1) { Bm = B1; bias = bi1; C = C1; }
    else                      { Bm = B2; bias = bi2; C = C2; }

    __shared__ uint4 AsF[2][512];   // 8KB per buffer
    __shared__ uint4 BsF[2][512];   // 8KB per buffer

    const int tid  = threadIdx.x;
    const int warp = tid >> 5;
    const int lane = tid & 31;
    const int grp  = lane >> 2;
    const int q    = lane & 3;

    const int cRow = blockIdx.y * 128;
    const int cCol = blockIdx.x * 128;
    const int wm   = (warp & 3) * 32;
    const int wn   = (warp >> 2) * 64;
    const int ta   = (warp & 3) * 2;      // A m16-tile base for this warp
    const int ub   = (warp >> 2) * 4;     // B n8-pair base for this warp

    // gmem load mapping
    const int am = tid >> 2;              // 0..63 (+64)
    const int ak = (tid & 3) * 4;         // 0,4,8,12
    const int bk = tid >> 5;              // 0..7  (+8 -> kc=1)
    const int bn = lane * 4;              // 0..124

    const float* Ap = A  + (size_t)(cRow + am) * DD + ak;
    const float* Bp = Bm + (size_t)bk * DD + cCol + bn;

    // A scatter constants: k = ak+j -> kc=ak>>3 fixed, kh=(ak>>2)&1 fixed, q_=j
    const int kcA = ak >> 3;
    const int khA = (ak >> 2) & 1;
    // B scatter constants: rows bk (kc=0) and bk+8 (kc=1): q_=bk&3, kh=bk>>2
    const int qB = bk & 3;
    const int khB = bk >> 2;

    float acc[2][8][4];
#pragma unroll
    for (int mi = 0; mi < 2; mi++)
#pragma unroll
        for (int ni = 0; ni < 8; ni++)
#pragma unroll
            for (int c = 0; c < 4; c++) acc[mi][ni][c] = 0.f;

    // ---- staging helpers (write into uint32 view of fragment buffers) ----
    // A element (row m, k=ak+j): idx = (kcA*8 + m/16)*128 + (m&7)*16 + j*4
    //                                   + khA*2 + ((m>>3)&1)
    // B element (kc, col n=bn+j): idx = (kc*8 + n/16)*128 + (n&7)*16 + qB*4
    //                                   + ((n>>3)&1)*2 + khB
#define STAGE_A(DST, M, V)                                                   \
    {                                                                        \
        float _vv[4] = {(V).x, (V).y, (V).z, (V).w};                         \
        uint32_t* _d = (uint32_t*)(DST);                                     \
        int _b = (kcA * 8 + ((M) >> 4)) * 128 + ((M) & 7) * 16 + khA * 2 +   \
                 (((M) >> 3) & 1);                                           \
        _Pragma("unroll") for (int _j = 0; _j < 4; _j++)                     \
            _d[_b + _j * 4] = f2tf32(_vv[_j]);                               \
    }
#define STAGE_B(DST, KC, V)                                                  \
    {                                                                        \
        float _vv[4] = {(V).x, (V).y, (V).z, (V).w};                         \
        uint32_t* _d = (uint32_t*)(DST);                                     \
        _Pragma("unroll") for (int _j = 0; _j < 4; _j++) {                   \
            int _n = bn + _j;                                                \
            _d[(KC * 8 + (_n >> 4)) * 128 + (_n & 7) * 16 + qB * 4 +         \
               ((_n >> 3) & 1) * 2 + khB] = f2tf32(_vv[_j]);                 \
        }                                                                    \
    }

    // ---- prologue: tile 0 ----
    {
        float4 a0 = *(const float4*)(Ap);
        float4 a1 = *(const float4*)(Ap + 64 * DD);
        float4 b0 = *(const float4*)(Bp);
        float4 b1 = *(const float4*)(Bp + 8 * DD);
        STAGE_A(AsF[0], am, a0);
        STAGE_A(AsF[0], am + 64, a1);
        STAGE_B(BsF[0], 0, b0);
        STAGE_B(BsF[0], 1, b1);
    }
    __syncthreads();

    int buf = 0;
    for (int k0 = 0; k0 < DD; k0 += 16) {
        const bool has_next = (k0 + 16 < DD);
        float4 pa0, pa1, pb0, pb1;
        if (has_next) {
            const int kn = k0 + 16;
            pa0 = *(const float4*)(Ap + kn);
            pa1 = *(const float4*)(Ap + 64 * DD + kn);
            pb0 = *(const float4*)(Bp + (size_t)kn * DD);
            pb1 = *(const float4*)(Bp + (size_t)(kn + 8) * DD);
        }

        const uint4* as = AsF[buf];
        const uint4* bs = BsF[buf];
#pragma unroll
        for (int kc = 0; kc < 2; kc++) {
            uint4 a0 = as[(kc * 8 + ta) * 32 + lane];
            uint4 a1 = as[(kc * 8 + ta + 1) * 32 + lane];
            uint4 bv[4];
#pragma unroll
            for (int i = 0; i < 4; i++)
                bv[i] = bs[(kc * 8 + ub + i) * 32 + lane];
#pragma unroll
            for (int i = 0; i < 4; i++) {
                MMA_TF32(acc[0][2 * i],     a0.x, a0.y, a0.z, a0.w, bv[i].x, bv[i].y);
                MMA_TF32(acc[0][2 * i + 1], a0.x, a0.y, a0.z, a0.w, bv[i].z, bv[i].w);
                MMA_TF32(acc[1][2 * i],     a1.x, a1.y, a1.z, a1.w, bv[i].x, bv[i].y);
                MMA_TF32(acc[1][2 * i + 1], a1.x, a1.y, a1.z, a1.w, bv[i].z, bv[i].w);
            }
        }

        if (has_next) {
            STAGE_A(AsF[buf ^ 1], am, pa0);
            STAGE_A(AsF[buf ^ 1], am + 64, pa1);
            STAGE_B(BsF[buf ^ 1], 0, pb0);
            STAGE_B(BsF[buf ^ 1], 1, pb1);
            __syncthreads();
            buf ^= 1;
        }
    }

    // ---- epilogue: bias + store ----
#pragma unroll
    for (int mi = 0; mi < 2; mi++) {
#pragma unroll
        for (int ni = 0; ni < 8; ni++) {
            int row = cRow + wm + mi * 16 + grp;
            int col = cCol + wn + ni * 8 + q * 2;
            float bx = bias[col], by = bias[col + 1];
            *(float2*)(C + (size_t)row * DD + col) =
                make_float2(acc[mi][ni][0] + bx, acc[mi][ni][1] + by);
            *(float2*)(C + (size_t)(row + 8) * DD + col) =
                make_float2(acc[mi][ni][2] + bx, acc[mi][ni][3] + by);
        }
    }
#undef STAGE_A
#undef STAGE_B
}

// ---------------------------------------------------------------------------
// Tensor-core causal flash attention (TF32 mma) — unchanged from R3.
// ---------------------------------------------------------------------------
constexpr int KST = 68;
constexpr int VST = 72;

__global__ __launch_bounds__(128, 3)
void flash_mma(const float* __restrict__ Qg, const float* __restrict__ Kg,
               const float* __restrict__ Vg, float* __restrict__ Og)
{
    __shared__ uint32_t Ksm[64 * KST];
    __shared__ uint32_t Vsm[64 * VST];

    const int tid  = threadIdx.x;
    const int warp = tid >> 5;
    const int lane = tid & 31;
    const int grp  = lane >> 2;
    const int q    = lane & 3;

    const int qb = 15 - blockIdx.y;
    const int i0 = qb * 64;
    const int h  = blockIdx.x & 15;
    const int b  = blockIdx.x >> 4;
    const size_t base = (size_t)b * (1024 * 1024) + h * 64;

    const int wm = warp * 16;
    const int r0 = i0 + wm + grp;

#pragma unroll
    for (int it = 0; it < 8; it++) {
        int idx = tid + it * 128;
        int row = idx >> 4;
        int c4  = (idx & 15) << 2;
        *(float4*)&((float*)Vsm)[row * VST + c4] =
            *(const float4*)(Qg + base + (size_t)(i0 + row) * DD + c4);
    }
    __syncthreads();
    uint32_t qf[8][4];
    {
        const float* Qs = (const float*)Vsm;
#pragma unroll
        for (int ks = 0; ks < 8; ks++) {
            qf[ks][0] = f2tf32(Qs[(wm + grp)     * VST + ks * 8 + q]);
            qf[ks][1] = f2tf32(Qs[(wm + grp + 8) * VST + ks * 8 + q]);
            qf[ks][2] = f2tf32(Qs[(wm + grp)     * VST + ks * 8 + q + 4]);
            qf[ks][3] = f2tf32(Qs[(wm + grp + 8) * VST + ks * 8 + q + 4]);
        }
    }
    __syncthreads();

    float oacc[8][4];
#pragma unroll
    for (int nt = 0; nt < 8; nt++)
#pragma unroll
        for (int c = 0; c < 4; c++) oacc[nt][c] = 0.f;
    float m0 = -1e30f, m1 = -1e30f, l0 = 0.f, l1 = 0.f;

    for (int jb = 0; jb <= qb; jb++) {
        const int j0 = jb * 64;

#pragma unroll
        for (int it = 0; it < 8; it++) {
            int idx = tid + it * 128;
            int row = idx >> 4;
            int c4  = (idx & 15) << 2;
            float4 k4 = *(const float4*)(Kg + base + (size_t)(j0 + row) * DD + c4);
            float4 v4 = *(const float4*)(Vg + base + (size_t)(j0 + row) * DD + c4);
            *(uint4*)&Ksm[row * KST + c4] =
                make_uint4(f2tf32(k4.x), f2tf32(k4.y), f2tf32(k4.z), f2tf32(k4.w));
            *(uint4*)&Vsm[row * VST + c4] =
                make_uint4(f2tf32(v4.x), f2tf32(v4.y), f2tf32(v4.z), f2tf32(v4.w));
        }
        __syncthreads();

        float sacc[8][4];
#pragma unroll
        for (int nt = 0; nt < 8; nt++)
#pragma unroll
            for (int c = 0; c < 4; c++) sacc[nt][c] = 0.f;
#pragma unroll
        for (int ks = 0; ks < 8; ks++) {
            uint32_t bf[8][2];
#pragma unroll
            for (int nt = 0; nt < 8; nt++) {
                bf[nt][0] = Ksm[(nt * 8 + grp) * KST + ks * 8 + q];
                bf[nt][1] = Ksm[(nt * 8 + grp) * KST + ks * 8 + q + 4];
            }
#pragma unroll
            for (int nt = 0; nt < 8; nt++)
                MMA_TF32V(sacc[nt], qf[ks], bf[nt]);
        }

        const bool diag = (jb == qb);
        float mx0 = -1e30f, mx1 = -1e30f;
#pragma unroll
        for (int nt = 0; nt < 8; nt++) {
            float s0 = sacc[nt][0] * 0.125f;
            float s1 = sacc[nt][1] * 0.125f;
            float s2 = sacc[nt][2] * 0.125f;
            float s3 = sacc[nt][3] * 0.125f;
            if (diag) {
                int j = j0 + nt * 8 + q * 2;
                if (j     > r0)     s0 = -1e30f;
                if (j + 1 > r0)     s1 = -1e30f;
                if (j     > r0 + 8) s2 = -1e30f;
                if (j + 1 > r0 + 8) s3 = -1e30f;
            }
            sacc[nt][0] = s0; sacc[nt][1] = s1;
            sacc[nt][2] = s2; sacc[nt][3] = s3;
            mx0 = fmaxf(mx0, fmaxf(s0, s1));
            mx1 = fmaxf(mx1, fmaxf(s2, s3));
        }
        mx0 = fmaxf(mx0, __shfl_xor_sync(0xffffffffu, mx0, 1));
        mx0 = fmaxf(mx0, __shfl_xor_sync(0xffffffffu, mx0, 2));
        mx1 = fmaxf(mx1, __shfl_xor_sync(0xffffffffu, mx1, 1));
        mx1 = fmaxf(mx1, __shfl_xor_sync(0xffffffffu, mx1, 2));
        float mn0 = fmaxf(m0, mx0), mn1 = fmaxf(m1, mx1);
        float al0 = __expf(m0 - mn0), al1 = __expf(m1 - mn1);
        m0 = mn0; m1 = mn1;
        float ps0 = 0.f, ps1 = 0.f;
#pragma unroll
        for (int nt = 0; nt < 8; nt++) {
            float p0 = __expf(sacc[nt][0] - mn0);
            float p1 = __expf(sacc[nt][1] - mn0);
            float p2 = __expf(sacc[nt][2] - mn1);
            float p3 = __expf(sacc[nt][3] - mn1);
            ps0 += p0 + p1;
            ps1 += p2 + p3;
            sacc[nt][0] = p0; sacc[nt][1] = p1;
            sacc[nt][2] = p2; sacc[nt][3] = p3;
        }
        l0 = l0 * al0 + ps0;
        l1 = l1 * al1 + ps1;
#pragma unroll
        for (int nt = 0; nt < 8; nt++) {
            oacc[nt][0] *= al0; oacc[nt][1] *= al0;
            oacc[nt][2] *= al1; oacc[nt][3] *= al1;
        }

        __syncthreads();

        uint32_t* Psm = Ksm + wm * KST;
#pragma unroll
        for (int nt = 0; nt < 8; nt++) {
            *(uint2*)&Psm[grp * KST + nt * 8 + q * 2] =
                make_uint2(f2tf32(sacc[nt][0]), f2tf32(sacc[nt][1]));
            *(uint2*)&Psm[(grp + 8) * KST + nt * 8 + q * 2] =
                make_uint2(f2tf32(sacc[nt][2]), f2tf32(sacc[nt][3]));
        }
        __syncwarp();

#pragma unroll
        for (int ks = 0; ks < 8; ks++) {
            uint32_t af[4];
            af[0] = Psm[grp * KST + ks * 8 + q];
            af[1] = Psm[(grp + 8) * KST + ks * 8 + q];
            af[2] = Psm[grp * KST + ks * 8 + q + 4];
            af[3] = Psm[(grp + 8) * KST + ks * 8 + q + 4];
            uint32_t bf[8][2];
#pragma unroll
            for (int nt = 0; nt < 8; nt++) {
                bf[nt][0] = Vsm[(ks * 8 + q) * VST + nt * 8 + grp];
                bf[nt][1] = Vsm[(ks * 8 + q + 4) * VST + nt * 8 + grp];
            }
#pragma unroll
            for (int nt = 0; nt < 8; nt++)
                MMA_TF32V(oacc[nt], af, bf[nt]);
        }
        __syncthreads();
    }

    l0 += __shfl_xor_sync(0xffffffffu, l0, 1);
    l0 += __shfl_xor_sync(0xffffffffu, l0, 2);
    l1 += __shfl_xor_sync(0xffffffffu, l1, 1);
    l1 += __shfl_xor_sync(0xffffffffu, l1, 2);
    const float inv0 = 1.f / l0;
    const float inv1 = 1.f / l1;
#pragma unroll
    for (int nt = 0; nt < 8; nt++) {
        int col = nt * 8 + q * 2;
        *(float2*)(Og + base + (size_t)r0 * DD + col) =
            make_float2(oacc[nt][0] * inv0, oacc[nt][1] * inv0);
        *(float2*)(Og + base + (size_t)(r0 + 8) * DD + col) =
            make_float2(oacc[nt][2] * inv1, oacc[nt][3] * inv1);
    }
}

// ---------------------------------------------------------------------------
extern "C" void kernel_launch(void* const* d_in, const int* in_sizes, int n_in,
                              void* d_out, int out_size)
{
    (void)in_sizes; (void)n_in; (void)out_size;
    const float* x  = (const float*)d_in[0];
    const float* wq = (const float*)d_in[2];
    const float* bq = (const float*)d_in[3];
    const float* wk = (const float*)d_in[4];
    const float* bk = (const float*)d_in[5];
    const float* wv = (const float*)d_in[6];
    const float* bv = (const float*)d_in[7];
    const float* wo = (const float*)d_in[8];
    const float* bo = (const float*)d_in[9];
    float* out = (float*)d_out;

    float *We, *Qb, *Kb, *Vb, *Ob;
    cudaGetSymbolAddress((void**)&We, g_We);
    cudaGetSymbolAddress((void**)&Qb, g_Q);
    cudaGetSymbolAddress((void**)&Kb, g_K);
    cudaGetSymbolAddress((void**)&Vb, g_V);
    cudaGetSymbolAddress((void**)&Ob, g_O);

    expand_kernel<<<dim3(DD * DD / 256, 4), 256>>>(wq, wk, wv, wo);

    gemm_tf32<<<dim3(DD / 128, MM / 128, 3), 256>>>(
        x, We, We + DD * DD, We + 2 * DD * DD, bq, bk, bv, Qb, Kb, Vb);

    flash_mma<<<dim3(32, 16), 128>>>(Qb, Kb, Vb, Ob);

    gemm_tf32<<<dim3(DD / 128, MM / 128, 1), 256>>>(
        Ob, We + 3 * DD * DD, We + 3 * DD * DD, We + 3 * DD * DD,
        bo, bo, bo, out, out, out);
}

// round 7
// speedup vs baseline: 1.7535x; 1.7535x over previous
#include <cuda_runtime.h>
#include <cstdint>

// ---------------------------------------------------------------------------
// B=2, N=1024, D=1024, K=8 (circulant), H=16, dh=64
// circ_linear == dense GEMM with W[p*8+i][q*8+j] = w[p,q,(i-j) mod 8]
// Weights are expanded TRANSPOSED: Wt[n][k] = W[k][n]  (k contiguous)
// ---------------------------------------------------------------------------
constexpr int DD = 1024;
constexpr int MM = 2048;

__device__ float g_We[4][DD * DD];   // expanded weights, layout Wt[n][k]
__device__ float g_Q[MM * DD];
__device__ float g_K[MM * DD];
__device__ float g_V[MM * DD];
__device__ float g_O[MM * DD];

__device__ __forceinline__ uint32_t f2tf32(float f) {
    uint32_t r;
    asm("cvt.rna.tf32.f32 %0, %1;" : "=r"(r) : "f"(f));
    return r;
}

#define MMA_TF32(ACC, A0, A1, A2, A3, B0, B1)                            \
    asm volatile(                                                        \
        "mma.sync.aligned.m16n8k8.row.col.f32.tf32.tf32.f32 "            \
        "{%0,%1,%2,%3}, {%4,%5,%6,%7}, {%8,%9}, {%0,%1,%2,%3};"          \
        : "+f"((ACC)[0]), "+f"((ACC)[1]), "+f"((ACC)[2]), "+f"((ACC)[3]) \
        : "r"(A0), "r"(A1), "r"(A2), "r"(A3), "r"(B0), "r"(B1))

#define MMA_TF32V(ACC, AF, BF)                                           \
    MMA_TF32(ACC, (AF)[0], (AF)[1], (AF)[2], (AF)[3], (BF)[0], (BF)[1])

#define LDSM4(R0, R1, R2, R3, ADDR)                                      \
    asm volatile("ldmatrix.sync.aligned.m8n8.x4.shared.b16 "             \
                 "{%0,%1,%2,%3}, [%4];"                                  \
                 : "=r"(R0), "=r"(R1), "=r"(R2), "=r"(R3) : "r"(ADDR))

// ---------------------------------------------------------------------------
// Expand circulant blocks TRANSPOSED: dst[n][k] = w[n/8][k/8][(n-k)&7]
// ---------------------------------------------------------------------------
__global__ void expand_kernel(const float* __restrict__ w0,
                              const float* __restrict__ w1,
                              const float* __restrict__ w2,
                              const float* __restrict__ w3)
{
    const float* w;
    switch (blockIdx.y) {
        case 0:  w = w0; break;
        case 1:  w = w1; break;
        case 2:  w = w2; break;
        default: w = w3; break;
    }
    float* dst = g_We[blockIdx.y];
    int idx = blockIdx.x * 256 + threadIdx.x;
    int n = idx >> 10;
    int k = idx & 1023;
    dst[idx] = w[((n >> 3) << 10) + ((k >> 3) << 3) + ((n - k) & 7)];
}

// ---------------------------------------------------------------------------
// TF32 GEMM + bias via ldmatrix fragments.
// C[2048,1024] = A[M,K] * Wt[N,K]^T + bias. Tile 128x128, BK=16, 8 warps
// of 32x64. Smem: A [m][k] stride 20, B [n][k] stride 20 (both k-contig,
// tf32-converted at staging). All fragment loads are LDSM.x4.
// ---------------------------------------------------------------------------
constexpr int GST = 20;                    // smem row stride (floats)
constexpr int BUFW = 128 * GST;            // words per buffer

__global__ __launch_bounds__(256, 2)
void gemm_tf32(const float* __restrict__ A,
               const float* __restrict__ B0, const float* __restrict__ B1,
               const float* __restrict__ B2,
               const float* __restrict__ bi0, const float* __restrict__ bi1,
               const float* __restrict__ bi2,
               float* __restrict__ C0, float* __restrict__ C1,
               float* __restrict__ C2)
{
    const float* Bm; const float* bias; float* C;
    if (blockIdx.z == 0)      { Bm = B0; bias = bi0; C = C0; }
    else if (blockIdx.z == 1) { Bm = B1; bias = bi1; C = C1; }
    else                      { Bm = B2; bias = bi2; C = C2; }

    __shared__ uint32_t As[2 * BUFW];
    __shared__ uint32_t Bs[2 * BUFW];

    const int tid  = threadIdx.x;
    const int warp = tid >> 5;
    const int lane = tid & 31;
    const int grp  = lane >> 2;
    const int q    = lane & 3;

    const int cRow = blockIdx.y * 128;
    const int cCol = blockIdx.x * 128;
    const int wm   = (warp & 3) * 32;
    const int wn   = (warp >> 2) * 64;

    // staging map: row = tid>>2 (0..63, +64), col4 = (tid&3)*4
    const int sr = tid >> 2;
    const int sc = (tid & 3) * 4;

    const float* Ap = A  + (size_t)(cRow + sr) * DD + sc;
    const float* Bp = Bm + (size_t)(cCol + sr) * DD + sc;

    uint32_t* As0 = As + sr * GST + sc;
    uint32_t* Bs0 = Bs + sr * GST + sc;

    // ldmatrix per-lane base addresses (byte offsets into As/Bs buffer 0)
    const uint32_t aBase = (uint32_t)__cvta_generic_to_shared(As);
    const uint32_t bBase = (uint32_t)__cvta_generic_to_shared(Bs);
    // A tile mi: row = wm + mi*16 + (lane&15), +16B if lane>=16 (k 4..7)
    uint32_t aAddr[2];
#pragma unroll
    for (int mi = 0; mi < 2; mi++)
        aAddr[mi] = aBase + ((wm + mi * 16 + (lane & 15)) * GST) * 4 +
                    (lane >> 4) * 16;
    // B pair p: tile = 2p + (lane>>4), n = wn + tile*8 + (lane&7),
    //           +16B if (lane>>3)&1 (k 4..7)
    uint32_t bAddr[4];
#pragma unroll
    for (int p = 0; p < 4; p++)
        bAddr[p] = bBase + ((wn + (2 * p + (lane >> 4)) * 8 + (lane & 7)) * GST) * 4 +
                   ((lane >> 3) & 1) * 16;

    float acc[2][8][4];
#pragma unroll
    for (int mi = 0; mi < 2; mi++)
#pragma unroll
        for (int ni = 0; ni < 8; ni++)
#pragma unroll
            for (int c = 0; c < 4; c++) acc[mi][ni][c] = 0.f;

#define STAGE(DST, V)                                                        \
    *(uint4*)(DST) = make_uint4(f2tf32((V).x), f2tf32((V).y),                \
                                f2tf32((V).z), f2tf32((V).w))

    // ---- prologue: tile 0 ----
    {
        float4 a0 = *(const float4*)(Ap);
        float4 a1 = *(const float4*)(Ap + 64 * DD);
        float4 b0 = *(const float4*)(Bp);
        float4 b1 = *(const float4*)(Bp + 64 * DD);
        STAGE(As0, a0);
        STAGE(As0 + 64 * GST, a1);
        STAGE(Bs0, b0);
        STAGE(Bs0 + 64 * GST, b1);
    }
    __syncthreads();

    int buf = 0;
    for (int k0 = 0; k0 < DD; k0 += 16) {
        const bool has_next = (k0 + 16 < DD);
        float4 pa0, pa1, pb0, pb1;
        if (has_next) {
            const int kn = k0 + 16;
            pa0 = *(const float4*)(Ap + kn);
            pa1 = *(const float4*)(Ap + 64 * DD + kn);
            pb0 = *(const float4*)(Bp + kn);
            pb1 = *(const float4*)(Bp + 64 * DD + kn);
        }

        const uint32_t bo = buf * (BUFW * 4);   // byte offset of buffer
#pragma unroll
        for (int kc = 0; kc < 2; kc++) {
            const uint32_t ko = bo + kc * 32;   // kk=8 -> +32 bytes
            uint32_t a0[4], a1[4];
            LDSM4(a0[0], a0[1], a0[2], a0[3], aAddr[0] + ko);
            LDSM4(a1[0], a1[1], a1[2], a1[3], aAddr[1] + ko);
            uint32_t bv[4][4];
#pragma unroll
            for (int p = 0; p < 4; p++)
                LDSM4(bv[p][0], bv[p][1], bv[p][2], bv[p][3], bAddr[p] + ko);
#pragma unroll
            for (int p = 0; p < 4; p++) {
                MMA_TF32(acc[0][2 * p],     a0[0], a0[1], a0[2], a0[3], bv[p][0], bv[p][1]);
                MMA_TF32(acc[0][2 * p + 1], a0[0], a0[1], a0[2], a0[3], bv[p][2], bv[p][3]);
                MMA_TF32(acc[1][2 * p],     a1[0], a1[1], a1[2], a1[3], bv[p][0], bv[p][1]);
                MMA_TF32(acc[1][2 * p + 1], a1[0], a1[1], a1[2], a1[3], bv[p][2], bv[p][3]);
            }
        }

        if (has_next) {
            uint32_t* asn = As0 + (buf ^ 1) * BUFW;
            uint32_t* bsn = Bs0 + (buf ^ 1) * BUFW;
            STAGE(asn, pa0);
            STAGE(asn + 64 * GST, pa1);
            STAGE(bsn, pb0);
            STAGE(bsn + 64 * GST, pb1);
            __syncthreads();
            buf ^= 1;
        }
    }
#undef STAGE

    // ---- epilogue: bias + store ----
#pragma unroll
    for (int mi = 0; mi < 2; mi++) {
#pragma unroll
        for (int ni = 0; ni < 8; ni++) {
            int row = cRow + wm + mi * 16 + grp;
            int col = cCol + wn + ni * 8 + q * 2;
            float bx = bias[col], by = bias[col + 1];
            *(float2*)(C + (size_t)row * DD + col) =
                make_float2(acc[mi][ni][0] + bx, acc[mi][ni][1] + by);
            *(float2*)(C + (size_t)(row + 8) * DD + col) =
                make_float2(acc[mi][ni][2] + bx, acc[mi][ni][3] + by);
        }
    }
}

// ---------------------------------------------------------------------------
// Tensor-core causal flash attention (TF32 mma) — unchanged from R3.
// ---------------------------------------------------------------------------
constexpr int KST = 68;
constexpr int VST = 72;

__global__ __launch_bounds__(128, 3)
void flash_mma(const float* __restrict__ Qg, const float* __restrict__ Kg,
               const float* __restrict__ Vg, float* __restrict__ Og)
{
    __shared__ uint32_t Ksm[64 * KST];
    __shared__ uint32_t Vsm[64 * VST];

    const int tid  = threadIdx.x;
    const int warp = tid >> 5;
    const int lane = tid & 31;
    const int grp  = lane >> 2;
    const int q    = lane & 3;

    const int qb = 15 - blockIdx.y;
    const int i0 = qb * 64;
    const int h  = blockIdx.x & 15;
    const int b  = blockIdx.x >> 4;
    const size_t base = (size_t)b * (1024 * 1024) + h * 64;

    const int wm = warp * 16;
    const int r0 = i0 + wm + grp;

#pragma unroll
    for (int it = 0; it < 8; it++) {
        int idx = tid + it * 128;
        int row = idx >> 4;
        int c4  = (idx & 15) << 2;
        *(float4*)&((float*)Vsm)[row * VST + c4] =
            *(const float4*)(Qg + base + (size_t)(i0 + row) * DD + c4);
    }
    __syncthreads();
    uint32_t qf[8][4];
    {
        const float* Qs = (const float*)Vsm;
#pragma unroll
        for (int ks = 0; ks < 8; ks++) {
            qf[ks][0] = f2tf32(Qs[(wm + grp)     * VST + ks * 8 + q]);
            qf[ks][1] = f2tf32(Qs[(wm + grp + 8) * VST + ks * 8 + q]);
            qf[ks][2] = f2tf32(Qs[(wm + grp)     * VST + ks * 8 + q + 4]);
            qf[ks][3] = f2tf32(Qs[(wm + grp + 8) * VST + ks * 8 + q + 4]);
        }
    }
    __syncthreads();

    float oacc[8][4];
#pragma unroll
    for (int nt = 0; nt < 8; nt++)
#pragma unroll
        for (int c = 0; c < 4; c++) oacc[nt][c] = 0.f;
    float m0 = -1e30f, m1 = -1e30f, l0 = 0.f, l1 = 0.f;

    for (int jb = 0; jb <= qb; jb++) {
        const int j0 = jb * 64;

#pragma unroll
        for (int it = 0; it < 8; it++) {
            int idx = tid + it * 128;
            int row = idx >> 4;
            int c4  = (idx & 15) << 2;
            float4 k4 = *(const float4*)(Kg + base + (size_t)(j0 + row) * DD + c4);
            float4 v4 = *(const float4*)(Vg + base + (size_t)(j0 + row) * DD + c4);
            *(uint4*)&Ksm[row * KST + c4] =
                make_uint4(f2tf32(k4.x), f2tf32(k4.y), f2tf32(k4.z), f2tf32(k4.w));
            *(uint4*)&Vsm[row * VST + c4] =
                make_uint4(f2tf32(v4.x), f2tf32(v4.y), f2tf32(v4.z), f2tf32(v4.w));
        }
        __syncthreads();

        float sacc[8][4];
#pragma unroll
        for (int nt = 0; nt < 8; nt++)
#pragma unroll
            for (int c = 0; c < 4; c++) sacc[nt][c] = 0.f;
#pragma unroll
        for (int ks = 0; ks < 8; ks++) {
            uint32_t bf[8][2];
#pragma unroll
            for (int nt = 0; nt < 8; nt++) {
                bf[nt][0] = Ksm[(nt * 8 + grp) * KST + ks * 8 + q];
                bf[nt][1] = Ksm[(nt * 8 + grp) * KST + ks * 8 + q + 4];
            }
#pragma unroll
            for (int nt = 0; nt < 8; nt++)
                MMA_TF32V(sacc[nt], qf[ks], bf[nt]);
        }

        const bool diag = (jb == qb);
        float mx0 = -1e30f, mx1 = -1e30f;
#pragma unroll
        for (int nt = 0; nt < 8; nt++) {
            float s0 = sacc[nt][0] * 0.125f;
            float s1 = sacc[nt][1] * 0.125f;
            float s2 = sacc[nt][2] * 0.125f;
            float s3 = sacc[nt][3] * 0.125f;
            if (diag) {
                int j = j0 + nt * 8 + q * 2;
                if (j     > r0)     s0 = -1e30f;
                if (j + 1 > r0)     s1 = -1e30f;
                if (j     > r0 + 8) s2 = -1e30f;
                if (j + 1 > r0 + 8) s3 = -1e30f;
            }
            sacc[nt][0] = s0; sacc[nt][1] = s1;
            sacc[nt][2] = s2; sacc[nt][3] = s3;
            mx0 = fmaxf(mx0, fmaxf(s0, s1));
            mx1 = fmaxf(mx1, fmaxf(s2, s3));
        }
        mx0 = fmaxf(mx0, __shfl_xor_sync(0xffffffffu, mx0, 1));
        mx0 = fmaxf(mx0, __shfl_xor_sync(0xffffffffu, mx0, 2));
        mx1 = fmaxf(mx1, __shfl_xor_sync(0xffffffffu, mx1, 1));
        mx1 = fmaxf(mx1, __shfl_xor_sync(0xffffffffu, mx1, 2));
        float mn0 = fmaxf(m0, mx0), mn1 = fmaxf(m1, mx1);
        float al0 = __expf(m0 - mn0), al1 = __expf(m1 - mn1);
        m0 = mn0; m1 = mn1;
        float ps0 = 0.f, ps1 = 0.f;
#pragma unroll
        for (int nt = 0; nt < 8; nt++) {
            float p0 = __expf(sacc[nt][0] - mn0);
            float p1 = __expf(sacc[nt][1] - mn0);
            float p2 = __expf(sacc[nt][2] - mn1);
            float p3 = __expf(sacc[nt][3] - mn1);
            ps0 += p0 + p1;
            ps1 += p2 + p3;
            sacc[nt][0] = p0; sacc[nt][1] = p1;
            sacc[nt][2] = p2; sacc[nt][3] = p3;
        }
        l0 = l0 * al0 + ps0;
        l1 = l1 * al1 + ps1;
#pragma unroll
        for (int nt = 0; nt < 8; nt++) {
            oacc[nt][0] *= al0; oacc[nt][1] *= al0;
            oacc[nt][2] *= al1; oacc[nt][3] *= al1;
        }

        __syncthreads();

        uint32_t* Psm = Ksm + wm * KST;
#pragma unroll
        for (int nt = 0; nt < 8; nt++) {
            *(uint2*)&Psm[grp * KST + nt * 8 + q * 2] =
                make_uint2(f2tf32(sacc[nt][0]), f2tf32(sacc[nt][1]));
            *(uint2*)&Psm[(grp + 8) * KST + nt * 8 + q * 2] =
                make_uint2(f2tf32(sacc[nt][2]), f2tf32(sacc[nt][3]));
        }
        __syncwarp();

#pragma unroll
        for (int ks = 0; ks < 8; ks++) {
            uint32_t af[4];
            af[0] = Psm[grp * KST + ks * 8 + q];
            af[1] = Psm[(grp + 8) * KST + ks * 8 + q];
            af[2] = Psm[grp * KST + ks * 8 + q + 4];
            af[3] = Psm[(grp + 8) * KST + ks * 8 + q + 4];
            uint32_t bf[8][2];
#pragma unroll
            for (int nt = 0; nt < 8; nt++) {
                bf[nt][0] = Vsm[(ks * 8 + q) * VST + nt * 8 + grp];
                bf[nt][1] = Vsm[(ks * 8 + q + 4) * VST + nt * 8 + grp];
            }
#pragma unroll
            for (int nt = 0; nt < 8; nt++)
                MMA_TF32V(oacc[nt], af, bf[nt]);
        }
        __syncthreads();
    }

    l0 += __shfl_xor_sync(0xffffffffu, l0, 1);
    l0 += __shfl_xor_sync(0xffffffffu, l0, 2);
    l1 += __shfl_xor_sync(0xffffffffu, l1, 1);
    l1 += __shfl_xor_sync(0xffffffffu, l1, 2);
    const float inv0 = 1.f / l0;
    const float inv1 = 1.f / l1;
#pragma unroll
    for (int nt = 0; nt < 8; nt++) {
        int col = nt * 8 + q * 2;
        *(float2*)(Og + base + (size_t)r0 * DD + col) =
            make_float2(oacc[nt][0] * inv0, oacc[nt][1] * inv0);
        *(float2*)(Og + base + (size_t)(r0 + 8) * DD + col) =
            make_float2(oacc[nt][2] * inv1, oacc[nt][3] * inv1);
    }
}

// ---------------------------------------------------------------------------
extern "C" void kernel_launch(void* const* d_in, const int* in_sizes, int n_in,
                              void* d_out, int out_size)
{
    (void)in_sizes; (void)n_in; (void)out_size;
    const float* x  = (const float*)d_in[0];
    const float* wq = (const float*)d_in[2];
    const float* bq = (const float*)d_in[3];
    const float* wk = (const float*)d_in[4];
    const float* bk = (const float*)d_in[5];
    const float* wv = (const float*)d_in[6];
    const float* bv = (const float*)d_in[7];
    const float* wo = (const float*)d_in[8];
    const float* bo = (const float*)d_in[9];
    float* out = (float*)d_out;

    float *We, *Qb, *Kb, *Vb, *Ob;
    cudaGetSymbolAddress((void**)&We, g_We);
    cudaGetSymbolAddress((void**)&Qb, g_Q);
    cudaGetSymbolAddress((void**)&Kb, g_K);
    cudaGetSymbolAddress((void**)&Vb, g_V);
    cudaGetSymbolAddress((void**)&Ob, g_O);

    expand_kernel<<<dim3(DD * DD / 256, 4), 256>>>(wq, wk, wv, wo);

    gemm_tf32<<<dim3(DD / 128, MM / 128, 3), 256>>>(
        x, We, We + DD * DD, We + 2 * DD * DD, bq, bk, bv, Qb, Kb, Vb);

    flash_mma<<<dim3(32, 16), 128>>>(Qb, Kb, Vb, Ob);

    gemm_tf32<<<dim3(DD / 128, MM / 128, 1), 256>>>(
        Ob, We + 3 * DD * DD, We + 3 * DD * DD, We + 3 * DD * DD,
        bo, bo, bo, out, out, out);
}